// round 15
// baseline (speedup 1.0000x reference)
#include <cuda_runtime.h>
#include <cuda_fp16.h>

#define B_  4
#define S_  1024
#define H_  16
#define D_  64
#define E_  1024
#define P_  1024
#define NS_ 2048
#define K_  1024

__device__ __align__(16) __half g_x16[B_ * S_ * E_];
__device__ __align__(16) __half g_wa16[E_ * 3 * E_];
__device__ __align__(16) __half g_wp16[E_ * E_];
__device__ __align__(16) __half g_Qh16[B_ * H_ * S_ * D_];     // Q [B,H,S,D] f16
__device__ __align__(16) __half g_attn16[B_ * S_ * E_];        // attn out f16
__device__ __align__(16) __half g_kv16[2 * B_ * H_ * NS_ * D_]; // f16 mirror of present

// ---------------- helpers ----------------
__device__ __forceinline__ unsigned pack_f16(float lo, float hi) {
    unsigned r; asm("cvt.rn.f16x2.f32 %0, %1, %2;" : "=r"(r) : "f"(hi), "f"(lo)); return r;
}
__device__ __forceinline__ float ex2f(float x) {
    float r; asm("ex2.approx.ftz.f32 %0, %1;" : "=f"(r) : "f"(x)); return r;
}
__device__ __forceinline__ unsigned h2exp(unsigned x) {
    unsigned r; asm("ex2.approx.f16x2 %0, %1;" : "=r"(r) : "r"(x)); return r;
}
__device__ __forceinline__ void mma_f16(float* d, const unsigned* a, const unsigned* b) {
    asm volatile("mma.sync.aligned.m16n8k16.row.col.f32.f16.f16.f32 "
        "{%0,%1,%2,%3}, {%4,%5,%6,%7}, {%8,%9}, {%0,%1,%2,%3};"
        : "+f"(d[0]), "+f"(d[1]), "+f"(d[2]), "+f"(d[3])
        : "r"(a[0]), "r"(a[1]), "r"(a[2]), "r"(a[3]), "r"(b[0]), "r"(b[1]));
}
__device__ __forceinline__ unsigned su(const void* p) {
    return (unsigned)__cvta_generic_to_shared(p);
}
__device__ __forceinline__ void cp16(unsigned s, const void* g) {
    asm volatile("cp.async.ca.shared.global [%0], [%1], 16;" :: "r"(s), "l"(g));
}
__device__ __forceinline__ void cp_commit() {
    asm volatile("cp.async.commit_group;" ::: "memory");
}
template <int N> __device__ __forceinline__ void cp_wait() {
    asm volatile("cp.async.wait_group %0;" :: "n"(N) : "memory");
}
__device__ __forceinline__ void ldsm_x4(unsigned* d, unsigned addr) {
    asm volatile("ldmatrix.sync.aligned.m8n8.x4.shared.b16 {%0,%1,%2,%3}, [%4];"
        : "=r"(d[0]), "=r"(d[1]), "=r"(d[2]), "=r"(d[3]) : "r"(addr));
}
__device__ __forceinline__ void ldsm_x4_trans(unsigned* d, unsigned addr) {
    asm volatile("ldmatrix.sync.aligned.m8n8.x4.trans.shared.b16 {%0,%1,%2,%3}, [%4];"
        : "=r"(d[0]), "=r"(d[1]), "=r"(d[2]), "=r"(d[3]) : "r"(addr));
}

// ---------------- f32 -> f16 conversion (x, w_attn, w_proj) ----------------
__global__ __launch_bounds__(256) void convert_kernel(const float* __restrict__ x,
                                                      const float* __restrict__ wa,
                                                      const float* __restrict__ wp)
{
    const int NX4 = (B_ * S_ * E_) / 4;
    const int NWA4 = (E_ * 3 * E_) / 4;
    const int NWP4 = (E_ * E_) / 4;
    int gs = gridDim.x * blockDim.x;
    for (int i = blockIdx.x * blockDim.x + threadIdx.x; i < NX4 + NWA4 + NWP4; i += gs) {
        const float4* s; unsigned* d;
        if (i < NX4) { s = (const float4*)x + i; d = (unsigned*)g_x16 + i * 2; }
        else if (i < NX4 + NWA4) { int j = i - NX4; s = (const float4*)wa + j; d = (unsigned*)g_wa16 + j * 2; }
        else { int j = i - NX4 - NWA4; s = (const float4*)wp + j; d = (unsigned*)g_wp16 + j * 2; }
        float4 v = *s;
        d[0] = pack_f16(v.x, v.y);
        d[1] = pack_f16(v.z, v.w);
    }
}

// ---------------- pipelined f16 GEMM: 4-stage ring, 32k stages, ldsm ops ----
#define AROW 40    // halfwords per A smem row (32 data + 8 pad = 80B)
#define BROW 136   // halfwords per B smem row (128 data + 8 pad = 272B)
#define ASTG (128 * AROW)
#define BSTG (32 * BROW)
#define GEMM_SMEM_BYTES (4 * (ASTG + BSTG) * 2)
__global__ __launch_bounds__(256) void gemm_f16_kernel(
    const float* __restrict__ bias, float* __restrict__ Cout,
    float* __restrict__ present, int N, int qkv_mode,
    const float* __restrict__ past)
{
    if (qkv_mode && (int)blockIdx.x >= (N >> 7)) {
        int part = ((int)blockIdx.x - (N >> 7)) * (int)gridDim.y + (int)blockIdx.y; // 0..127
        const float4* src = (const float4*)(past + (size_t)part * (P_ * D_));
        float4* dst = (float4*)(present + (size_t)part * (NS_ * D_));
        uint2* dst16 = (uint2*)(g_kv16 + (size_t)part * (NS_ * D_));
#pragma unroll 4
        for (int i = threadIdx.x; i < (P_ * D_) / 4; i += 256) {
            float4 v = src[i];
            dst[i] = v;
            dst16[i] = make_uint2(pack_f16(v.x, v.y), pack_f16(v.z, v.w));
        }
        return;
    }

    const __half* A = qkv_mode ? g_x16 : g_attn16;
    const __half* Bw = qkv_mode ? g_wa16 : g_wp16;

    extern __shared__ __align__(16) __half sm16[];
    __half* Asb = sm16;               // 4 stages of ASTG
    __half* Bsb = sm16 + 4 * ASTG;    // 4 stages of BSTG

    int t = threadIdx.x;
    int bm = blockIdx.y * 128, bn = blockIdx.x * 128;
    int w = t >> 5, l = t & 31;
    int wm = (w & 1) * 64, wn = (w >> 1) * 32;
    int r = l >> 2, c = l & 3;

    float acc[4][4][4];
#pragma unroll
    for (int i = 0; i < 4; i++)
#pragma unroll
        for (int j = 0; j < 4; j++)
#pragma unroll
            for (int k = 0; k < 4; k++) acc[i][j][k] = 0.f;

    int a_srow = t >> 1, a_scol = (t & 1) * 16;
    int b_srow = t >> 4, b_scol = (t & 15) * 8;
    const __half* Ag = A + (size_t)(bm + a_srow) * K_ + a_scol;
    const __half* Bg = Bw + (size_t)b_srow * N + bn + b_scol;
    unsigned a_dst = a_srow * AROW + a_scol;
    unsigned b_dst = b_srow * BROW + b_scol;

    int lm16 = l & 15, lmc = (l >> 4) * 8;

    // prologue: stages 0,1,2
#pragma unroll
    for (int p = 0; p < 3; p++) {
        int k0 = p * 32;
        cp16(su(Asb + p * ASTG + a_dst), Ag + k0);
        cp16(su(Asb + p * ASTG + a_dst + 8), Ag + k0 + 8);
        cp16(su(Bsb + p * BSTG + b_dst), Bg + (size_t)k0 * N);
        cp16(su(Bsb + p * BSTG + b_dst + 16 * BROW), Bg + (size_t)(k0 + 16) * N);
        cp_commit();
    }

    const int NIT = K_ / 32;   // 32
    for (int it = 0; it < NIT; ++it) {
        int buf = it & 3;
        cp_wait<2>();
        __syncthreads();

        if (it + 3 < NIT) {
            int nb = (it + 3) & 3, k0 = (it + 3) * 32;
            cp16(su(Asb + nb * ASTG + a_dst), Ag + k0);
            cp16(su(Asb + nb * ASTG + a_dst + 8), Ag + k0 + 8);
            cp16(su(Bsb + nb * BSTG + b_dst), Bg + (size_t)k0 * N);
            cp16(su(Bsb + nb * BSTG + b_dst + 16 * BROW), Bg + (size_t)(k0 + 16) * N);
        }
        cp_commit();

        const __half* Ab = Asb + buf * ASTG;
        const __half* Bb = Bsb + buf * BSTG;
#pragma unroll
        for (int kk = 0; kk < 32; kk += 16) {
            unsigned af[4][4], bf[2][4];
#pragma unroll
            for (int mi = 0; mi < 4; mi++)
                ldsm_x4(af[mi], su(Ab + (wm + mi * 16 + lm16) * AROW + kk + lmc));
            ldsm_x4_trans(bf[0], su(Bb + (kk + lm16) * BROW + wn + lmc));
            ldsm_x4_trans(bf[1], su(Bb + (kk + lm16) * BROW + wn + lmc + 16));
#pragma unroll
            for (int mi = 0; mi < 4; mi++)
#pragma unroll
                for (int ni = 0; ni < 4; ni++)
                    mma_f16(acc[mi][ni], af[mi], &bf[ni >> 1][(ni & 1) * 2]);
        }
    }

    // epilogue
#pragma unroll
    for (int mi = 0; mi < 4; mi++) {
#pragma unroll
        for (int ni = 0; ni < 4; ni++) {
            int row0 = bm + wm + mi * 16 + r;
            int col = bn + wn + ni * 8 + 2 * c;
#pragma unroll
            for (int half = 0; half < 2; half++) {
                int row = row0 + half * 8;
                float v0 = acc[mi][ni][half * 2 + 0] + bias[col];
                float v1 = acc[mi][ni][half * 2 + 1] + bias[col + 1];
                if (!qkv_mode) {
                    *(float2*)&Cout[(size_t)row * N + col] = make_float2(v0, v1);
                } else {
                    int b = row >> 10, s = row & 1023;
                    int part = col >> 10, nn = col & 1023;
                    int h = nn >> 6, d = nn & 63;
                    if (part == 0) {
                        *(unsigned*)&g_Qh16[(((size_t)(b * H_ + h) * S_) + s) * D_ + d] =
                            pack_f16(v0, v1);
                    } else {
                        int cbh = (part == 1) ? (b * H_ + h) : ((B_ + b) * H_ + h);
                        size_t idx = ((size_t)cbh * NS_ + P_ + s) * D_ + d;
                        *(float2*)&present[idx] = make_float2(v0, v1);
                        *(unsigned*)&g_kv16[idx] = pack_f16(v0, v1);
                    }
                }
            }
        }
    }
}

// ---------------- fp16 flash attention (heavy tiles launched first) --------
#define KVROW 72   // halfwords per smem row (64 data + 8 pad = 144B)
__global__ __launch_bounds__(256) void attn_mma_kernel()
{
    __shared__ __align__(16) __half Ks[2][64][KVROW];
    __shared__ __align__(16) __half Vs[2][64][KVROW];

    int t = threadIdx.x, w = t >> 5, l = t & 31;
    int r = l >> 2, c = l & 3;
    int bh = blockIdx.y;
    int q0 = ((int)gridDim.x - 1 - (int)blockIdx.x) * 128;   // heavy first
    int b = bh >> 4, h = bh & 15;

    const __half* Kb = g_kv16 + (size_t)bh * (NS_ * D_);
    const __half* Vb = g_kv16 + (size_t)(B_ * H_ + bh) * (NS_ * D_);

    const float SC = 0.125f * 1.4426950408889634f;
    unsigned qf[4][4];
    {
        const __half* Qp = g_Qh16 + ((size_t)bh * S_ + q0 + w * 16) * D_;
#pragma unroll
        for (int kc = 0; kc < 4; kc++) {
            int base = kc * 16;
            qf[kc][0] = *(const unsigned*)(Qp + (size_t)r * D_ + base + 2 * c);
            qf[kc][1] = *(const unsigned*)(Qp + (size_t)(r + 8) * D_ + base + 2 * c);
            qf[kc][2] = *(const unsigned*)(Qp + (size_t)r * D_ + base + 8 + 2 * c);
            qf[kc][3] = *(const unsigned*)(Qp + (size_t)(r + 8) * D_ + base + 8 + 2 * c);
        }
    }

    float o[8][4];
#pragma unroll
    for (int i = 0; i < 8; i++)
#pragma unroll
        for (int j = 0; j < 4; j++) o[i][j] = 0.f;
    const float NEG = __int_as_float(0xff800000);
    float m0 = NEG, m1 = NEG, l0 = 0.f, l1 = 0.f;

    int srow = t >> 2, sch = (t & 3) * 2;
    unsigned ks_dst0 = su(&Ks[0][srow][0]);
    unsigned vs_dst0 = su(&Vs[0][srow][0]);
    const int SMEM_BUF = 64 * KVROW * 2;

    unsigned v_lm0 = su(&Vs[0][l & 15][(l >> 4) * 8]);

    {
        const __half* kg = Kb + (size_t)srow * D_ + sch * 8;
        const __half* vg = Vb + (size_t)srow * D_ + sch * 8;
        cp16(ks_dst0 + sch * 16, kg);
        cp16(ks_dst0 + sch * 16 + 16, kg + 8);
        cp16(vs_dst0 + sch * 16, vg);
        cp16(vs_dst0 + sch * 16 + 16, vg + 8);
        cp_commit();
    }

    int ntiles = (P_ + q0 + 128) / 64;
    for (int it = 0; it < ntiles; ++it) {
        int buf = it & 1;
        cp_wait<0>();
        __syncthreads();

        if (it + 1 < ntiles) {
            int jn = (it + 1) * 64;
            unsigned off = (buf ^ 1) ? SMEM_BUF : 0;
            const __half* kg = Kb + (size_t)(jn + srow) * D_ + sch * 8;
            const __half* vg = Vb + (size_t)(jn + srow) * D_ + sch * 8;
            cp16(ks_dst0 + off + sch * 16, kg);
            cp16(ks_dst0 + off + sch * 16 + 16, kg + 8);
            cp16(vs_dst0 + off + sch * 16, vg);
            cp16(vs_dst0 + off + sch * 16 + 16, vg + 8);
        }
        cp_commit();

        float s[8][4];
#pragma unroll
        for (int nt = 0; nt < 8; nt++)
            s[nt][0] = s[nt][1] = s[nt][2] = s[nt][3] = 0.f;
#pragma unroll
        for (int kc = 0; kc < 4; kc++) {
#pragma unroll
            for (int nt = 0; nt < 8; nt++) {
                unsigned bf[2] = {
                    *(const unsigned*)&Ks[buf][nt * 8 + r][kc * 16 + 2 * c],
                    *(const unsigned*)&Ks[buf][nt * 8 + r][kc * 16 + 8 + 2 * c]
                };
                mma_f16(s[nt], qf[kc], bf);
            }
        }

        int j0 = it * 64;
        int qrow = q0 + w * 16 + r;
        int lim0 = P_ + qrow - j0;
        int lim1 = lim0 + 8;
#pragma unroll
        for (int nt = 0; nt < 8; nt++) {
            int j = nt * 8 + 2 * c;
            s[nt][0] = (j > lim0) ? NEG : s[nt][0] * SC;
            s[nt][1] = (j + 1 > lim0) ? NEG : s[nt][1] * SC;
            s[nt][2] = (j > lim1) ? NEG : s[nt][2] * SC;
            s[nt][3] = (j + 1 > lim1) ? NEG : s[nt][3] * SC;
        }

        float mx0 = NEG, mx1 = NEG;
#pragma unroll
        for (int nt = 0; nt < 8; nt++) {
            mx0 = fmaxf(mx0, fmaxf(s[nt][0], s[nt][1]));
            mx1 = fmaxf(mx1, fmaxf(s[nt][2], s[nt][3]));
        }
        mx0 = fmaxf(mx0, __shfl_xor_sync(0xffffffffu, mx0, 1));
        mx0 = fmaxf(mx0, __shfl_xor_sync(0xffffffffu, mx0, 2));
        mx1 = fmaxf(mx1, __shfl_xor_sync(0xffffffffu, mx1, 1));
        mx1 = fmaxf(mx1, __shfl_xor_sync(0xffffffffu, mx1, 2));
        float nm0 = fmaxf(m0, mx0), nm1 = fmaxf(m1, mx1);
        float a0 = ex2f(m0 - nm0), a1 = ex2f(m1 - nm1);
        m0 = nm0; m1 = nm1;
        l0 *= a0; l1 *= a1;
#pragma unroll
        for (int nt = 0; nt < 8; nt++) {
            o[nt][0] *= a0; o[nt][1] *= a0;
            o[nt][2] *= a1; o[nt][3] *= a1;
        }

        unsigned vb = v_lm0 + (buf ? SMEM_BUF : 0);
#pragma unroll
        for (int ks = 0; ks < 4; ks++) {
            unsigned ap[4];
            ap[0] = h2exp(pack_f16(s[2 * ks][0] - nm0, s[2 * ks][1] - nm0));
            ap[1] = h2exp(pack_f16(s[2 * ks][2] - nm1, s[2 * ks][3] - nm1));
            ap[2] = h2exp(pack_f16(s[2 * ks + 1][0] - nm0, s[2 * ks + 1][1] - nm0));
            ap[3] = h2exp(pack_f16(s[2 * ks + 1][2] - nm1, s[2 * ks + 1][3] - nm1));
            float2 f0 = __half22float2(*(__half2*)&ap[0]);
            float2 f1 = __half22float2(*(__half2*)&ap[1]);
            float2 f2 = __half22float2(*(__half2*)&ap[2]);
            float2 f3 = __half22float2(*(__half2*)&ap[3]);
            l0 += f0.x + f0.y + f2.x + f2.y;
            l1 += f1.x + f1.y + f3.x + f3.y;
#pragma unroll
            for (int pair = 0; pair < 4; pair++) {
                unsigned v[4];
                ldsm_x4_trans(v, vb + ks * 16 * (KVROW * 2) + pair * 32);
                mma_f16(o[2 * pair], ap, v);
                mma_f16(o[2 * pair + 1], ap, v + 2);
            }
        }
        __syncthreads();
    }

    l0 += __shfl_xor_sync(0xffffffffu, l0, 1);
    l0 += __shfl_xor_sync(0xffffffffu, l0, 2);
    l1 += __shfl_xor_sync(0xffffffffu, l1, 1);
    l1 += __shfl_xor_sync(0xffffffffu, l1, 2);
    float inv0 = 1.f / l0, inv1 = 1.f / l1;

    int qrow = q0 + w * 16 + r;
    __half* dst0 = g_attn16 + ((size_t)(b * S_ + qrow)) * E_ + h * D_;
    __half* dst1 = dst0 + (size_t)8 * E_;
#pragma unroll
    for (int nt = 0; nt < 8; nt++) {
        int cc = nt * 8 + 2 * c;
        *(unsigned*)(dst0 + cc) = pack_f16(o[nt][0] * inv0, o[nt][1] * inv0);
        *(unsigned*)(dst1 + cc) = pack_f16(o[nt][2] * inv1, o[nt][3] * inv1);
    }
}

// ---------------------------------------------------------------------------
extern "C" void kernel_launch(void* const* d_in, const int* in_sizes, int n_in,
                              void* d_out, int out_size)
{
    (void)in_sizes; (void)n_in; (void)out_size;
    const float* x      = (const float*)d_in[0];
    const float* past   = (const float*)d_in[1];
    const float* w_attn = (const float*)d_in[2];
    const float* b_attn = (const float*)d_in[3];
    const float* w_proj = (const float*)d_in[4];
    const float* b_proj = (const float*)d_in[5];

    float* out     = (float*)d_out;
    float* present = out + (size_t)B_ * S_ * E_;

    static int smem_set = 0;
    if (!smem_set) {
        cudaFuncSetAttribute(gemm_f16_kernel,
                             cudaFuncAttributeMaxDynamicSharedMemorySize,
                             GEMM_SMEM_BYTES);
        smem_set = 1;
    }

    convert_kernel<<<1024, 256>>>(x, w_attn, w_proj);
    gemm_f16_kernel<<<dim3(3 * E_ / 128 + 4, (B_ * S_) / 128), 256, GEMM_SMEM_BYTES>>>(
        b_attn, nullptr, present, 3 * E_, 1, past);
    attn_mma_kernel<<<dim3(S_ / 128, B_ * H_), 256>>>();
    gemm_f16_kernel<<<dim3(E_ / 128, (B_ * S_) / 128), 256, GEMM_SMEM_BYTES>>>(
        b_proj, out, nullptr, E_, 0, nullptr);
}